// round 13
// baseline (speedup 1.0000x reference)
#include <cuda_runtime.h>

#define N_MENTIONS 65536
#define D 256
#define LANES 64              // threads per mention group (64 x float4 = 256 floats)
#define GROUPS_PER_BLOCK 2    // 128 threads per block (best measured config)
#define NUM_BLOCKS 2368       // 148 SMs x 16 CTAs/SM: exact full residency

// Scratch: CSR row pointers built each launch (allocation-free requirement).
__device__ int g_row_ptr[N_MENTIONS + 1];

// Prologue: boundary-fill row_ptr from sorted COO rows, int4-vectorized.
__global__ __launch_bounds__(256)
void build_rowptr_kernel(const int4* __restrict__ spm_rows4, int nnz)
{
    int t = blockIdx.x * blockDim.x + threadIdx.x;
    int j0 = t * 4;
    if (j0 >= nnz) return;

    const int4 r4 = __ldg(spm_rows4 + t);
    int rp;
    if (j0 == 0) rp = -1;
    else         rp = __ldg(((const int*)spm_rows4) + j0 - 1);

    int rr[4] = {r4.x, r4.y, r4.z, r4.w};
    #pragma unroll
    for (int k = 0; k < 4; ++k) {
        const int r = rr[k];
        for (int row = rp + 1; row <= r; ++row) g_row_ptr[row] = j0 + k;
        rp = r;
    }
    if (j0 + 4 >= nnz) {
        for (int row = rp + 1; row <= N_MENTIONS; ++row) g_row_ptr[row] = nnz;
    }
}

// Persistent grid-stride kernel: each 64-thread group walks groups with stride
// (NUM_BLOCKS * GROUPS_PER_BLOCK), prefetching the NEXT group's row_ptr bounds
// before running the current group's gather loop — the bounds latency hides
// under the gathers, and CTA setup/retire cost is paid 2368x instead of 32768x.
__global__ __launch_bounds__(LANES * GROUPS_PER_BLOCK)
void mention_segsum_kernel(const float4* __restrict__ token_ft,   // [N_TOKENS, 64] float4
                           const int*    __restrict__ token_code, // [NNZ]
                           const float*  __restrict__ spm_vals,   // [NNZ]
                           float4*       __restrict__ out)        // [N_MENTIONS, 64] float4
{
    const int lane   = threadIdx.x & (LANES - 1);
    const int stride = NUM_BLOCKS * GROUPS_PER_BLOCK;

    int g = blockIdx.x * GROUPS_PER_BLOCK + (threadIdx.x / LANES);

    int s = __ldg(g_row_ptr + g);
    int e = __ldg(g_row_ptr + g + 1);

    for (; g < N_MENTIONS; ) {
        // Prefetch next group's bounds NOW; they resolve while we gather.
        const int gn = g + stride;
        int sn = 0, en = 0;
        if (gn < N_MENTIONS) {
            sn = __ldg(g_row_ptr + gn);
            en = __ldg(g_row_ptr + gn + 1);
        }

        float4 acc = make_float4(0.f, 0.f, 0.f, 0.f);

        // 4-wide dense mainloop: 4 independent 1KB row gathers in flight.
        int j = s;
        for (; j + 3 < e; j += 4) {
            const int   c0 = __ldcs(token_code + j);
            const int   c1 = __ldcs(token_code + j + 1);
            const int   c2 = __ldcs(token_code + j + 2);
            const int   c3 = __ldcs(token_code + j + 3);
            const float v0 = __ldcs(spm_vals + j);
            const float v1 = __ldcs(spm_vals + j + 1);
            const float v2 = __ldcs(spm_vals + j + 2);
            const float v3 = __ldcs(spm_vals + j + 3);
            const float4 f0 = __ldcg(token_ft + (size_t)c0 * (D / 4) + lane);
            const float4 f1 = __ldcg(token_ft + (size_t)c1 * (D / 4) + lane);
            const float4 f2 = __ldcg(token_ft + (size_t)c2 * (D / 4) + lane);
            const float4 f3 = __ldcg(token_ft + (size_t)c3 * (D / 4) + lane);
            acc.x += v0 * f0.x + v1 * f1.x + v2 * f2.x + v3 * f3.x;
            acc.y += v0 * f0.y + v1 * f1.y + v2 * f2.y + v3 * f3.y;
            acc.z += v0 * f0.z + v1 * f1.z + v2 * f2.z + v3 * f3.z;
            acc.w += v0 * f0.w + v1 * f1.w + v2 * f2.w + v3 * f3.w;
        }
        if (j + 1 < e) {
            const int   c0 = __ldcs(token_code + j);
            const int   c1 = __ldcs(token_code + j + 1);
            const float v0 = __ldcs(spm_vals + j);
            const float v1 = __ldcs(spm_vals + j + 1);
            const float4 f0 = __ldcg(token_ft + (size_t)c0 * (D / 4) + lane);
            const float4 f1 = __ldcg(token_ft + (size_t)c1 * (D / 4) + lane);
            acc.x += v0 * f0.x + v1 * f1.x;
            acc.y += v0 * f0.y + v1 * f1.y;
            acc.z += v0 * f0.z + v1 * f1.z;
            acc.w += v0 * f0.w + v1 * f1.w;
            j += 2;
        }
        if (j < e) {
            const int   c0 = __ldcs(token_code + j);
            const float v0 = __ldcs(spm_vals + j);
            const float4 f0 = __ldcg(token_ft + (size_t)c0 * (D / 4) + lane);
            acc.x += v0 * f0.x;
            acc.y += v0 * f0.y;
            acc.z += v0 * f0.z;
            acc.w += v0 * f0.w;
        }

        // One coalesced 1KB streaming store per mention row; empty segments
        // write zeros (poisoned output fully initialized).
        __stcs(out + (size_t)g * (D / 4) + lane, acc);

        g = gn; s = sn; e = en;
    }
}

extern "C" void kernel_launch(void* const* d_in, const int* in_sizes, int n_in,
                              void* d_out, int out_size)
{
    const float* token_ft   = (const float*)d_in[0]; // [262144, 256] f32
    const int*   token_code = (const int*)  d_in[1]; // [524288] i32
    const int*   spm_rows   = (const int*)  d_in[2]; // [524288] i32 sorted
    const float* spm_vals   = (const float*)d_in[3]; // [524288] f32
    float*       out        = (float*)d_out;         // [65536, 256] f32

    const int nnz = in_sizes[1];

    const int pro_threads = 256;
    const int pro_work    = (nnz + 3) / 4;
    build_rowptr_kernel<<<(pro_work + pro_threads - 1) / pro_threads, pro_threads>>>(
        (const int4*)spm_rows, nnz);

    mention_segsum_kernel<<<NUM_BLOCKS, LANES * GROUPS_PER_BLOCK>>>(
        (const float4*)token_ft, token_code, spm_vals, (float4*)out);
}

// round 14
// speedup vs baseline: 1.1132x; 1.1132x over previous
#include <cuda_runtime.h>

#define N_MENTIONS 65536
#define D 256
#define LANES 64              // threads per mention group (64 x float4 = 256 floats)
#define GROUPS_PER_BLOCK 2    // 128 threads per block (best measured config)

// Scratch: CSR row pointers built each launch (allocation-free requirement).
__device__ int g_row_ptr[N_MENTIONS + 1];

// Prologue: boundary-fill row_ptr from sorted COO rows, int4-vectorized.
__global__ __launch_bounds__(128)
void build_rowptr_kernel(const int4* __restrict__ spm_rows4, int nnz)
{
    int t = blockIdx.x * blockDim.x + threadIdx.x;
    int j0 = t * 4;
    if (j0 >= nnz) return;

    const int4 r4 = __ldg(spm_rows4 + t);
    int rp;
    if (j0 == 0) rp = -1;
    else         rp = __ldg(((const int*)spm_rows4) + j0 - 1);

    int rr[4] = {r4.x, r4.y, r4.z, r4.w};
    #pragma unroll
    for (int k = 0; k < 4; ++k) {
        const int r = rr[k];
        for (int row = rp + 1; row <= r; ++row) g_row_ptr[row] = j0 + k;
        rp = r;
    }
    if (j0 + 4 >= nnz) {
        for (int row = rp + 1; row <= N_MENTIONS; ++row) g_row_ptr[row] = nnz;
    }
}

__global__ __launch_bounds__(LANES * GROUPS_PER_BLOCK)
void mention_segsum_kernel(const float4* __restrict__ token_ft,   // [N_TOKENS, 64] float4
                           const int*    __restrict__ token_code, // [NNZ]
                           const float*  __restrict__ spm_vals,   // [NNZ]
                           float4*       __restrict__ out)        // [N_MENTIONS, 64] float4
{
    const int group = blockIdx.x * GROUPS_PER_BLOCK + (threadIdx.x / LANES);
    const int lane  = threadIdx.x & (LANES - 1);

    const int start = __ldg(g_row_ptr + group);
    const int end   = __ldg(g_row_ptr + group + 1);

    float4 acc = make_float4(0.f, 0.f, 0.f, 0.f);

    // 4-wide dense mainloop: 4 independent 1KB row gathers in flight per warp.
    // __ldcs on indices/vals: single-use streams, evict-first preserves L2 for
    //   the token table. __ldcg on gathers: L2-only, no intra-SM reuse.
    int j = start;
    for (; j + 3 < end; j += 4) {
        const int   c0 = __ldcs(token_code + j);
        const int   c1 = __ldcs(token_code + j + 1);
        const int   c2 = __ldcs(token_code + j + 2);
        const int   c3 = __ldcs(token_code + j + 3);
        const float v0 = __ldcs(spm_vals + j);
        const float v1 = __ldcs(spm_vals + j + 1);
        const float v2 = __ldcs(spm_vals + j + 2);
        const float v3 = __ldcs(spm_vals + j + 3);
        const float4 f0 = __ldcg(token_ft + (size_t)c0 * (D / 4) + lane);
        const float4 f1 = __ldcg(token_ft + (size_t)c1 * (D / 4) + lane);
        const float4 f2 = __ldcg(token_ft + (size_t)c2 * (D / 4) + lane);
        const float4 f3 = __ldcg(token_ft + (size_t)c3 * (D / 4) + lane);
        acc.x += v0 * f0.x + v1 * f1.x + v2 * f2.x + v3 * f3.x;
        acc.y += v0 * f0.y + v1 * f1.y + v2 * f2.y + v3 * f3.y;
        acc.z += v0 * f0.z + v1 * f1.z + v2 * f2.z + v3 * f3.z;
        acc.w += v0 * f0.w + v1 * f1.w + v2 * f2.w + v3 * f3.w;
    }
    if (j + 1 < end) {
        const int   c0 = __ldcs(token_code + j);
        const int   c1 = __ldcs(token_code + j + 1);
        const float v0 = __ldcs(spm_vals + j);
        const float v1 = __ldcs(spm_vals + j + 1);
        const float4 f0 = __ldcg(token_ft + (size_t)c0 * (D / 4) + lane);
        const float4 f1 = __ldcg(token_ft + (size_t)c1 * (D / 4) + lane);
        acc.x += v0 * f0.x + v1 * f1.x;
        acc.y += v0 * f0.y + v1 * f1.y;
        acc.z += v0 * f0.z + v1 * f1.z;
        acc.w += v0 * f0.w + v1 * f1.w;
        j += 2;
    }
    if (j < end) {
        const int   c0 = __ldcs(token_code + j);
        const float v0 = __ldcs(spm_vals + j);
        const float4 f0 = __ldcg(token_ft + (size_t)c0 * (D / 4) + lane);
        acc.x += v0 * f0.x;
        acc.y += v0 * f0.y;
        acc.z += v0 * f0.z;
        acc.w += v0 * f0.w;
    }

    // One coalesced 1KB streaming store per mention row; empty segments write
    // zeros (poisoned output fully initialized).
    __stcs(out + (size_t)group * (D / 4) + lane, acc);
}

extern "C" void kernel_launch(void* const* d_in, const int* in_sizes, int n_in,
                              void* d_out, int out_size)
{
    const float* token_ft   = (const float*)d_in[0]; // [262144, 256] f32
    const int*   token_code = (const int*)  d_in[1]; // [524288] i32
    const int*   spm_rows   = (const int*)  d_in[2]; // [524288] i32 sorted
    const float* spm_vals   = (const float*)d_in[3]; // [524288] f32
    float*       out        = (float*)d_out;         // [65536, 256] f32

    const int nnz = in_sizes[1];

    const int pro_threads = 128;
    const int pro_work    = (nnz + 3) / 4;
    build_rowptr_kernel<<<(pro_work + pro_threads - 1) / pro_threads, pro_threads>>>(
        (const int4*)spm_rows, nnz);

    const int threads = LANES * GROUPS_PER_BLOCK;                                 // 128
    const int blocks  = N_MENTIONS / GROUPS_PER_BLOCK;                            // 32768

    mention_segsum_kernel<<<blocks, threads>>>(
        (const float4*)token_ft, token_code, spm_vals, (float4*)out);
}